// round 1
// baseline (speedup 1.0000x reference)
#include <cuda_runtime.h>
#include <cstdint>

// Problem constants (fixed by the dataset)
#define N_  50000
#define E_  600000
#define F_  64
#define H_  128
// concatenated GEMM: input dim 4*64=256, output dim 128(z)+128(h)=256
#define RDIM 256
#define CDIM 256

// ---------------- device scratch (static: no allocation allowed) ----------------
__device__ float g_deg[N_];            // degree, then dis = rsqrt(deg)
__device__ int   g_cnt[N_];            // in-degree counts (by dst)
__device__ int   g_cur[N_];            // scatter cursors
__device__ int   g_off[N_ + 1];        // CSR offsets (by dst)
__device__ int   g_csrc[E_];           // CSR: source node per slot
__device__ float g_cw[E_];             // CSR: normalized edge weight per slot
__device__ float g_T1[N_ * F_];
__device__ float g_T2[N_ * F_];
__device__ float g_T3[N_ * F_];
// W4 layout: for r-chunk q=r/4, block of 1024 floats:
//   g_W4[q*1024 + c*4 + (r&3)] = Wcat[r][c]
// Wcat[r][c]: r = k*64+f ; c<128 -> Wxz[k][f][c], c>=128 -> Wxh[k][f][c-128]
__device__ __align__(16) float g_W4[RDIM * CDIM];

// ---------------- setup kernels ----------------
__global__ void k_init() {
    int i = blockIdx.x * blockDim.x + threadIdx.x;
    if (i < N_) { g_deg[i] = 0.f; g_cnt[i] = 0; g_cur[i] = 0; }
}

__global__ void k_wcat(const float* __restrict__ Wxz, const float* __restrict__ Wxh) {
    int idx = blockIdx.x * blockDim.x + threadIdx.x;
    if (idx >= RDIM * CDIM) return;
    int q  = idx >> 10;          // r-chunk
    int rem = idx & 1023;
    int c  = rem >> 2;
    int rr = rem & 3;
    int r  = (q << 2) + rr;
    int k = r >> 6, f = r & 63;
    float v;
    if (c < H_) v = Wxz[k * F_ * H_ + f * H_ + c];
    else        v = Wxh[k * F_ * H_ + f * H_ + (c - H_)];
    g_W4[idx] = v;
}

// deg (by src) + in-degree counts (by dst)
__global__ void k_edge1(const int* __restrict__ ei, const float* __restrict__ ew) {
    int e = blockIdx.x * blockDim.x + threadIdx.x;
    if (e >= E_) return;
    int s = ei[e], d = ei[E_ + e];
    float w = (s == d) ? 0.f : ew[e];
    if (w != 0.f) atomicAdd(&g_deg[s], w);
    atomicAdd(&g_cnt[d], 1);
}

__global__ void k_dis() {
    int i = blockIdx.x * blockDim.x + threadIdx.x;
    if (i >= N_) return;
    float dg = g_deg[i];
    g_deg[i] = (dg > 0.f) ? rsqrtf(dg) : 0.f;
}

// single-block exclusive scan over g_cnt -> g_off
__global__ void k_scan() {
    const int TPB = 1024;
    __shared__ int ssum[TPB];
    int tid = threadIdx.x;
    const int chunk = (N_ + TPB - 1) / TPB;
    int beg = tid * chunk;
    int local = 0;
    for (int i = 0; i < chunk; i++) {
        int idx = beg + i;
        if (idx < N_) local += g_cnt[idx];
    }
    ssum[tid] = local;
    __syncthreads();
    for (int d = 1; d < TPB; d <<= 1) {
        int t = (tid >= d) ? ssum[tid - d] : 0;
        __syncthreads();
        if (tid >= d) ssum[tid] += t;
        __syncthreads();
    }
    int run = ssum[tid] - local;  // exclusive prefix at chunk start
    for (int i = 0; i < chunk; i++) {
        int idx = beg + i;
        if (idx < N_) { g_off[idx] = run; run += g_cnt[idx]; }
    }
    if (tid == TPB - 1) g_off[N_] = ssum[TPB - 1];
}

// fill CSR: normalized weight w_e = -dis[src]*ew*dis[dst] (self-loops removed)
__global__ void k_scatter(const int* __restrict__ ei, const float* __restrict__ ew) {
    int e = blockIdx.x * blockDim.x + threadIdx.x;
    if (e >= E_) return;
    int s = ei[e], d = ei[E_ + e];
    float w = (s == d) ? 0.f : ew[e];
    float we = -g_deg[s] * w * g_deg[d];   // g_deg holds dis here
    int pos = atomicAdd(&g_cur[d], 1);
    int o = g_off[d] + pos;
    g_csrc[o] = s;
    g_cw[o]   = we;
}

// ---------------- Chebyshev propagation (gather, no atomics) ----------------
// out[node] = coef * sum_{e in(node)} w_e * in[src_e]  -  sub[node]
// step 0: in=x,  sub=0,  out=T1, coef=1
// step 1: in=T1, sub=x,  out=T2, coef=2
// step 2: in=T2, sub=T1, out=T3, coef=2
__global__ void k_prop(const float* __restrict__ x, int step) {
    int t = blockIdx.x * blockDim.x + threadIdx.x;
    if (t >= N_ * 16) return;
    int node = t >> 4;
    int c    = (t & 15) << 2;

    const float* in;  const float* sub;  float* out;  float coef;
    if (step == 0)      { in = x;    sub = nullptr; out = g_T1; coef = 1.f; }
    else if (step == 1) { in = g_T1; sub = x;       out = g_T2; coef = 2.f; }
    else                { in = g_T2; sub = g_T1;    out = g_T3; coef = 2.f; }

    int beg = g_off[node], end = g_off[node + 1];
    float4 acc = make_float4(0.f, 0.f, 0.f, 0.f);
    for (int o = beg; o < end; o++) {
        int   s = g_csrc[o];
        float w = g_cw[o];
        float4 xv = *reinterpret_cast<const float4*>(in + (size_t)s * F_ + c);
        acc.x += w * xv.x; acc.y += w * xv.y;
        acc.z += w * xv.z; acc.w += w * xv.w;
    }
    float4 sv = make_float4(0.f, 0.f, 0.f, 0.f);
    if (sub) sv = *reinterpret_cast<const float4*>(sub + (size_t)node * F_ + c);
    float4 r;
    r.x = coef * acc.x - sv.x;  r.y = coef * acc.y - sv.y;
    r.z = coef * acc.z - sv.z;  r.w = coef * acc.w - sv.w;
    *reinterpret_cast<float4*>(out + (size_t)node * F_ + c) = r;
}

// ---------------- fused GEMM + GRU epilogue + output projection ----------------
// Block: 128 threads, 32 nodes. Thread j owns columns j (z) and j+128 (h).
// Accumulators are packed f32x2 pairs over the r dimension (fma.rn.f32x2);
// pairs are naturally contiguous in both sA (r-contiguous) and g_W4 layout.
__global__ void __launch_bounds__(128) k_gemm(
    const float* __restrict__ x,
    const float* __restrict__ bxz, const float* __restrict__ bhz,
    const float* __restrict__ bxh, const float* __restrict__ bhh,
    const float* __restrict__ linW, const float* __restrict__ linb,
    float* __restrict__ out)
{
    __shared__ __align__(16) float sA[32 * RDIM];   // 32 KB
    const int node0 = blockIdx.x * 32;
    const int tid = threadIdx.x;

    // load A tile: rows = 32 nodes, cols r = k*64+f over {x,T1,T2,T3}
    for (int idx = tid; idx < 32 * RDIM; idx += 128) {
        int i = idx >> 8, r = idx & 255;
        int node = node0 + i;
        float v = 0.f;
        if (node < N_) {
            int k = r >> 6, f = r & 63;
            const float* src = (k == 0) ? x : (k == 1) ? g_T1 : (k == 2) ? g_T2 : g_T3;
            v = src[(size_t)node * F_ + f];
        }
        sA[idx] = v;
    }
    __syncthreads();

    unsigned long long az[32], ah[32];
    #pragma unroll
    for (int i = 0; i < 32; i++) { az[i] = 0ULL; ah[i] = 0ULL; }

    #pragma unroll 1
    for (int r = 0; r < RDIM; r += 4) {
        const int q = r >> 2;
        ulonglong2 w0 = *reinterpret_cast<const ulonglong2*>(&g_W4[q * 1024 + tid * 4]);
        ulonglong2 w1 = *reinterpret_cast<const ulonglong2*>(&g_W4[q * 1024 + (tid + 128) * 4]);
        #pragma unroll
        for (int i = 0; i < 32; i++) {
            ulonglong2 a2 = *reinterpret_cast<const ulonglong2*>(&sA[i * RDIM + r]);
            asm("fma.rn.f32x2 %0, %1, %2, %0;" : "+l"(az[i]) : "l"(a2.x), "l"(w0.x));
            asm("fma.rn.f32x2 %0, %1, %2, %0;" : "+l"(az[i]) : "l"(a2.y), "l"(w0.y));
            asm("fma.rn.f32x2 %0, %1, %2, %0;" : "+l"(ah[i]) : "l"(a2.x), "l"(w1.x));
            asm("fma.rn.f32x2 %0, %1, %2, %0;" : "+l"(ah[i]) : "l"(a2.y), "l"(w1.y));
        }
    }

    const float bz = bxz[tid] + bhz[tid];
    const float bh = bxh[tid] + bhh[tid];
    const float lw = linW[tid];
    __syncthreads();                 // done reading sA; reuse as vals buffer

    float* vals = sA;                // needs 32*128 floats, fits
    #pragma unroll
    for (int i = 0; i < 32; i++) {
        float zlo = __uint_as_float((unsigned)(az[i] & 0xffffffffULL));
        float zhi = __uint_as_float((unsigned)(az[i] >> 32));
        float hlo = __uint_as_float((unsigned)(ah[i] & 0xffffffffULL));
        float hhi = __uint_as_float((unsigned)(ah[i] >> 32));
        float zin = zlo + zhi + bz;
        float hin = hlo + hhi + bh;
        float Z  = 1.f / (1.f + __expf(-zin));
        float Ht = tanhf(hin);
        float hv = (1.f - Z) * Ht;
        hv = fmaxf(hv, 0.f);
        vals[i * 128 + tid] = hv * lw;
    }
    __syncthreads();

    // reduce 128 lanes per node: 4 threads per node, rotated to avoid bank conflicts
    int i  = tid >> 2;
    int c4 = tid & 3;
    float s = 0.f;
    #pragma unroll
    for (int j = 0; j < 32; j++) {
        int jj = (j + tid) & 31;
        s += vals[i * 128 + c4 * 32 + jj];
    }
    s += __shfl_down_sync(0xffffffffu, s, 1);
    s += __shfl_down_sync(0xffffffffu, s, 2);
    if (c4 == 0) {
        int node = node0 + i;
        if (node < N_) out[node] = s + linb[0];
    }
}

// ---------------- launch ----------------
extern "C" void kernel_launch(void* const* d_in, const int* in_sizes, int n_in,
                              void* d_out, int out_size) {
    const float* x    = (const float*)d_in[0];
    const int*   ei   = (const int*)  d_in[1];
    const float* ew   = (const float*)d_in[2];
    const float* Wxz  = (const float*)d_in[3];
    const float* bxz  = (const float*)d_in[4];
    const float* bhz  = (const float*)d_in[6];   // Whz unused (h=0), only its bias
    const float* Wxh  = (const float*)d_in[11];
    const float* bxh  = (const float*)d_in[12];
    const float* bhh  = (const float*)d_in[14];  // Whh unused (h=0), only its bias
    const float* linW = (const float*)d_in[15];
    const float* linb = (const float*)d_in[16];
    float* out = (float*)d_out;

    k_init   <<<(N_ + 255) / 256, 256>>>();
    k_wcat   <<<(RDIM * CDIM + 255) / 256, 256>>>(Wxz, Wxh);
    k_edge1  <<<(E_ + 255) / 256, 256>>>(ei, ew);
    k_dis    <<<(N_ + 255) / 256, 256>>>();
    k_scan   <<<1, 1024>>>();
    k_scatter<<<(E_ + 255) / 256, 256>>>(ei, ew);
    k_prop   <<<(N_ * 16 + 255) / 256, 256>>>(x, 0);
    k_prop   <<<(N_ * 16 + 255) / 256, 256>>>(x, 1);
    k_prop   <<<(N_ * 16 + 255) / 256, 256>>>(x, 2);
    k_gemm   <<<(N_ + 31) / 32, 128>>>(x, bxz, bhz, bxh, bhh, linW, linb, out);
}